// round 15
// baseline (speedup 1.0000x reference)
#include <cuda_runtime.h>
#include <math.h>
#include <stdint.h>

// Problem constants (fixed by reference: N=32, C=256, H=W=32)
#define NB 32
#define CDIM 256
#define HW 1024
#define WD 32

// ---------------- device scratch (no allocations allowed) ----------------
__device__ double g_sum[64];                 // masked cos sum per (loss, n)
__device__ double g_cnt[64];                 // mask count per (loss, n)
__device__ float  g_ninv[4][NB * HW];        // 1/||.|| for p1,p2,z1,z2
__device__ float  g_cx[2][NB * HW];          // centers x for coord_1, coord_2
__device__ float  g_cy[2][NB * HW];          // centers y
__device__ float  g_dthr2[NB];               // EXACT d2 threshold (see below)
// TF32-quantized, transposed copies: [t][n][p][k], row = 256 floats (1KB).
__device__ float  g_tf32[4ull * NB * HW * CDIM];   // 134 MB

// Round fp32 -> TF32 (10-bit mantissa), same conversion cuBLAS/CUTLASS use.
__device__ __forceinline__ float tf32r(float x) {
    uint32_t u;
    asm("cvt.rna.tf32.f32 %0, %1;" : "=r"(u) : "f"(x));
    return __uint_as_float(u);
}

// m16n8k8 TF32 MMA, fp32 accumulate
__device__ __forceinline__ void mma_tf32(float* d,
                                         float a0, float a1, float a2, float a3,
                                         float b0, float b1) {
    asm volatile(
        "mma.sync.aligned.m16n8k8.row.col.f32.tf32.tf32.f32 "
        "{%0,%1,%2,%3}, {%4,%5,%6,%7}, {%8,%9}, {%0,%1,%2,%3};\n"
        : "+f"(d[0]), "+f"(d[1]), "+f"(d[2]), "+f"(d[3])
        : "r"(__float_as_uint(a0)), "r"(__float_as_uint(a1)),
          "r"(__float_as_uint(a2)), "r"(__float_as_uint(a3)),
          "r"(__float_as_uint(b0)), "r"(__float_as_uint(b1)));
}

#define CP_ASYNC16(dst32, srcp) \
    asm volatile("cp.async.cg.shared.global [%0], [%1], 16;\n" :: "r"(dst32), "l"(srcp))
#define CP_COMMIT() asm volatile("cp.async.commit_group;\n")
#define CP_WAIT(n)  asm volatile("cp.async.wait_group %0;\n" :: "n"(n))

// ---------------- kernels ----------------
__global__ void zero_kernel() {
    int i = threadIdx.x;
    if (i < 64) { g_sum[i] = 0.0; g_cnt[i] = 0.0; }
}

// grid (NB), block 1024: centers + EXACT d2 mask threshold.
// Reference mask  __fdiv_rn(__fsqrt_rn(d2), md) < 16  is monotone in d2, so
// a bit-level binary search yields T with mask <=> d2 < T, bit-exactly.
__global__ void centers_kernel(const float* __restrict__ c1, const float* __restrict__ c2) {
    int n = blockIdx.x;
    int p = threadIdx.x;
    float a0 = c1[n * 4 + 0], a1 = c1[n * 4 + 1], a2 = c1[n * 4 + 2], a3 = c1[n * 4 + 3];
    float b0 = c2[n * 4 + 0], b1 = c2[n * 4 + 1], b2 = c2[n * 4 + 2], b3 = c2[n * 4 + 3];
    float bw1 = __fdiv_rn(__fsub_rn(a2, a0), 32.0f), bh1 = __fdiv_rn(__fsub_rn(a3, a1), 32.0f);
    float bw2 = __fdiv_rn(__fsub_rn(b2, b0), 32.0f), bh2 = __fdiv_rn(__fsub_rn(b3, b1), 32.0f);
    float x = (float)(p % WD);
    float y = (float)(p / WD);
    g_cx[0][n * HW + p] = __fadd_rn(__fmul_rn(__fadd_rn(x, 0.5f), bw1), a0);
    g_cy[0][n * HW + p] = __fadd_rn(__fmul_rn(__fadd_rn(y, 0.5f), bh1), a1);
    g_cx[1][n * HW + p] = __fadd_rn(__fmul_rn(__fadd_rn(x, 0.5f), bw2), b0);
    g_cy[1][n * HW + p] = __fadd_rn(__fmul_rn(__fadd_rn(y, 0.5f), bh2), b1);
    if (p == 0) {
        float d1 = __fsqrt_rn(__fadd_rn(__fmul_rn(bw1, bw1), __fmul_rn(bh1, bh1)));
        float d2 = __fsqrt_rn(__fadd_rn(__fmul_rn(bw2, bw2), __fmul_rn(bh2, bh2)));
        float md = fmaxf(d1, d2);
        uint32_t lo = 0u, hi = 0x7F7FFFFFu;   // [0, FLT_MAX]
        while (lo < hi) {
            uint32_t mid = lo + ((hi - lo) >> 1);
            float v = __uint_as_float(mid);
            if (__fdiv_rn(__fsqrt_rn(v), md) >= 16.0f) hi = mid;
            else lo = mid + 1;
        }
        g_dthr2[n] = __uint_as_float(lo);     // mask <=> d2 < g_dthr2[n]
    }
}

// Fused prep: transpose [c][p] -> [p][c], TF32-quantize into g_tf32, AND
// accumulate exact-fp32 column norms (stored as inverses) in the same pass.
// grid (32 ptiles, NB, 4), block 256. 32x32 smem tile.
__global__ __launch_bounds__(256) void prep_kernel(
    const float* __restrict__ p1, const float* __restrict__ p2,
    const float* __restrict__ z1, const float* __restrict__ z2) {
    int t = blockIdx.z;
    int n = blockIdx.y;
    int p0 = blockIdx.x * 32;
    const float* src = (t == 0) ? p1 : (t == 1) ? p2 : (t == 2) ? z1 : z2;
    src += (size_t)n * CDIM * HW;
    float* dst = g_tf32 + ((size_t)(t * NB + n) * HW) * CDIM;

    __shared__ float s[32][33];
    __shared__ float part[8][32];
    int tid = threadIdx.x;
    int rc = tid >> 5;        // 0..7
    int rp = tid & 31;        // 0..31
    float acc = 0.f;

#pragma unroll 1
    for (int ct = 0; ct < 8; ++ct) {
        int c0 = ct * 32;
#pragma unroll
        for (int j = 0; j < 4; ++j) {
            int c = rc + j * 8;
            s[c][rp] = src[(size_t)(c0 + c) * HW + p0 + rp];
        }
        __syncthreads();
#pragma unroll
        for (int i = 0; i < 4; ++i) {
            float v = s[rc * 4 + i][rp];
            acc += v * v;
        }
#pragma unroll
        for (int j = 0; j < 4; ++j) {
            int p = rc + j * 8;
            dst[(size_t)(p0 + p) * CDIM + c0 + rp] = tf32r(s[rp][p]);
        }
        __syncthreads();
    }
    part[rc][rp] = acc;
    __syncthreads();
    if (tid < 32) {
        float n2 = 0.f;
#pragma unroll
        for (int g = 0; g < 8; ++g) n2 += part[g][tid];
        g_ninv[t][n * HW + p0 + tid] = 1.0f / sqrtf(n2);
    }
}

// Fused TF32 tensor-core GEMM + cosine + mask + masked-mean reduction.
// 128(p) x 128(q) tile, BK=32 (8 k-tiles), 3-stage cp.async ring (one
// barrier/stage). 8 warps (4M x 2N), warp tile 32x64. 2 CTAs/SM.
// B fragments processed in groups of 4 to cap live registers (no spills).
#define BM 128
#define BNQ 128
#define BK 32
#define NSTG 3
#define NT (CDIM / BK)    // 8 k-tiles
#define STAGE_A (BM * BK)              // 4096 floats (16 KB)
#define STAGE_B (BNQ * BK)             // 4096 floats (16 KB)
#define DYN_SMEM (NSTG * (STAGE_A + STAGE_B) * 4)   // 96 KB

__global__ __launch_bounds__(256, 2) void gemm_loss_kernel() {
    int z = blockIdx.z;          // 0..63 : (loss, n)
    int n = z & 31;
    int which = z >> 5;          // 0 -> (p1, z2), 1 -> (p2, z1)

    const float *Q, *K, *qiv, *kiv, *qcx, *qcy, *kcx, *kcy;
    if (which == 0) {
        Q = g_tf32 + ((size_t)(0 * NB + n) * HW) * CDIM;
        K = g_tf32 + ((size_t)(3 * NB + n) * HW) * CDIM;
        qiv = &g_ninv[0][n * HW]; kiv = &g_ninv[3][n * HW];
        qcx = &g_cx[0][n * HW]; qcy = &g_cy[0][n * HW];
        kcx = &g_cx[1][n * HW]; kcy = &g_cy[1][n * HW];
    } else {
        Q = g_tf32 + ((size_t)(1 * NB + n) * HW) * CDIM;
        K = g_tf32 + ((size_t)(2 * NB + n) * HW) * CDIM;
        qiv = &g_ninv[1][n * HW]; kiv = &g_ninv[2][n * HW];
        qcx = &g_cx[1][n * HW]; qcy = &g_cy[1][n * HW];
        kcx = &g_cx[0][n * HW]; kcy = &g_cy[0][n * HW];
    }
    float dthr2 = g_dthr2[n];

    extern __shared__ float dynsm[];
    float* Abase = dynsm;                         // NSTG stages of BM x BK
    float* Bbase = dynsm + NSTG * STAGE_A;        // NSTG stages of BNQ x BK
    __shared__ float warpS[8];
    __shared__ int   warpC[8];

    int tid  = threadIdx.x;
    int lane = tid & 31;
    int warp = tid >> 5;          // 0..7
    int gid  = lane >> 2;         // 0..7
    int tig  = lane & 3;          // 0..3
    int warpM = warp >> 1;        // 0..3 -> 32-row band
    int warpN = warp & 1;         // 0..1 -> 64-col band
    int pBase = blockIdx.x * BM;
    int qBase = blockIdx.y * BNQ;

    // cp.async mapping: row block cr + {0,32,64,96}, chunk col co (floats)
    int cr = tid >> 3;            // 0..31
    int co = (tid & 7) * 4;       // 0,4,...,28

    uint32_t sA = (uint32_t)__cvta_generic_to_shared(Abase);
    uint32_t sB = (uint32_t)__cvta_generic_to_shared(Bbase);
    const uint32_t aBuf = STAGE_A * 4;    // 16 KB
    const uint32_t bBuf = STAGE_B * 4;    // 16 KB
    const uint32_t rowB = BK * 4;         // 128 B per row
    uint32_t thOff = (uint32_t)((cr * BK + co) * 4);
    const float* qR = Q + (size_t)(pBase + cr) * CDIM + co;
    const float* kR = K + (size_t)(qBase + cr) * CDIM + co;

    float d[2][8][4];
#pragma unroll
    for (int mt = 0; mt < 2; ++mt)
#pragma unroll
        for (int nt = 0; nt < 8; ++nt)
#pragma unroll
            for (int r = 0; r < 4; ++r) d[mt][nt][r] = 0.f;

    // prologue: issue stages 0 and 1 as separate groups (8 cp.async each)
#pragma unroll
    for (int st = 0; st < 2; ++st) {
#pragma unroll
        for (int rb = 0; rb < 4; ++rb) {
            CP_ASYNC16(sA + st * aBuf + thOff + rb * 32u * rowB,
                       qR + (size_t)(rb * 32) * CDIM + st * BK);
            CP_ASYNC16(sB + st * bBuf + thOff + rb * 32u * rowB,
                       kR + (size_t)(rb * 32) * CDIM + st * BK);
        }
        CP_COMMIT();
    }

#pragma unroll
    for (int kt = 0; kt < NT; ++kt) {
        const int cur  = kt % NSTG;
        const int nxt2 = (kt + 2) % NSTG;
        if (kt < NT - 1) { CP_WAIT(1); } else { CP_WAIT(0); }
        __syncthreads();   // stage kt visible; fences reuse of buffer nxt2
        if (kt + 2 < NT) {
#pragma unroll
            for (int rb = 0; rb < 4; ++rb) {
                CP_ASYNC16(sA + nxt2 * aBuf + thOff + rb * 32u * rowB,
                           qR + (size_t)(rb * 32) * CDIM + (kt + 2) * BK);
                CP_ASYNC16(sB + nxt2 * bBuf + thOff + rb * 32u * rowB,
                           kR + (size_t)(rb * 32) * CDIM + (kt + 2) * BK);
            }
            CP_COMMIT();
        }
        const float* Acur = Abase + cur * STAGE_A;
        const float* Bcur = Bbase + cur * STAGE_B;
        // two k16 blocks per BK=32 tile
#pragma unroll
        for (int blk = 0; blk < 2; ++blk) {
            int kOff = blk * 16 + tig * 4;
            // A fragments for both mt (4 float4, covers both k8 steps)
            float4 va[2], vb[2];
#pragma unroll
            for (int mt = 0; mt < 2; ++mt) {
                int pm = warpM * 32 + mt * 16 + gid;
                va[mt] = *(const float4*)(Acur + pm * BK + kOff);
                vb[mt] = *(const float4*)(Acur + (pm + 8) * BK + kOff);
            }
            // B fragments in two groups of 4 (caps live registers)
#pragma unroll
            for (int ntg = 0; ntg < 2; ++ntg) {
                float4 wb[4];
#pragma unroll
                for (int j = 0; j < 4; ++j)
                    wb[j] = *(const float4*)(Bcur +
                        (warpN * 64 + (ntg * 4 + j) * 8 + gid) * BK + kOff);
#pragma unroll
                for (int mt = 0; mt < 2; ++mt) {
#pragma unroll
                    for (int j = 0; j < 4; ++j)
                        mma_tf32(d[mt][ntg * 4 + j],
                                 va[mt].x, vb[mt].x, va[mt].y, vb[mt].y,
                                 wb[j].x, wb[j].y);
#pragma unroll
                    for (int j = 0; j < 4; ++j)
                        mma_tf32(d[mt][ntg * 4 + j],
                                 va[mt].z, vb[mt].z, va[mt].w, vb[mt].w,
                                 wb[j].z, wb[j].w);
                }
            }
        }
    }

    // Epilogue. Premultiply accumulators by qinv (left-assoc identical to
    // d*qinv*kn), then cos = dpre*kn; mask = (d2 < dthr2) (bit-exact).
    float qnv[2][2], qxv[2][2], qyv[2][2];
#pragma unroll
    for (int mt = 0; mt < 2; ++mt)
#pragma unroll
        for (int i2 = 0; i2 < 2; ++i2) {
            int p = pBase + warpM * 32 + mt * 16 + gid + i2 * 8;
            qnv[mt][i2] = qiv[p]; qxv[mt][i2] = qcx[p]; qyv[mt][i2] = qcy[p];
        }
#pragma unroll
    for (int mt = 0; mt < 2; ++mt)
#pragma unroll
        for (int nt = 0; nt < 8; ++nt)
#pragma unroll
            for (int r = 0; r < 4; ++r)
                d[mt][nt][r] *= qnv[mt][r >> 1];

    float lsum = 0.f;
    int   icnt = 0;
#pragma unroll
    for (int nt = 0; nt < 8; ++nt) {
#pragma unroll
        for (int j2 = 0; j2 < 2; ++j2) {
            int q = qBase + warpN * 64 + nt * 8 + 2 * tig + j2;
            float kn = kiv[q], kx = kcx[q], ky = kcy[q];
#pragma unroll
            for (int mt = 0; mt < 2; ++mt) {
#pragma unroll
                for (int i2 = 0; i2 < 2; ++i2) {
                    float dx = __fsub_rn(qxv[mt][i2], kx);
                    float dy = __fsub_rn(qyv[mt][i2], ky);
                    float d2v = __fadd_rn(__fmul_rn(dx, dx), __fmul_rn(dy, dy));
                    if (d2v < dthr2) {
                        lsum += d[mt][nt][i2 * 2 + j2] * kn;
                        icnt += 1;
                    }
                }
            }
        }
    }

    // warp-shuffle reduction, then one cross-warp pass, then fp64 atomics
#pragma unroll
    for (int sh = 16; sh > 0; sh >>= 1) {
        lsum += __shfl_xor_sync(0xFFFFFFFFu, lsum, sh);
        icnt += __shfl_xor_sync(0xFFFFFFFFu, icnt, sh);
    }
    if (lane == 0) { warpS[warp] = lsum; warpC[warp] = icnt; }
    __syncthreads();
    if (warp == 0 && lane == 0) {
        float ts = 0.f; int tc = 0;
#pragma unroll
        for (int w = 0; w < 8; ++w) { ts += warpS[w]; tc += warpC[w]; }
        atomicAdd(&g_sum[z], (double)ts);
        atomicAdd(&g_cnt[z], (double)tc);
    }
}

__global__ void final_kernel(float* __restrict__ out) {
    double l1 = 0.0, l2 = 0.0;
    for (int n = 0; n < 32; ++n) {
        l1 += g_sum[n]      / (g_cnt[n]      + 1e-6);
        l2 += g_sum[32 + n] / (g_cnt[32 + n] + 1e-6);
    }
    out[0] = (float)(-((l1 / 32.0) + (l2 / 32.0)) * 0.5);
}

// ---------------- launch ----------------
extern "C" void kernel_launch(void* const* d_in, const int* in_sizes, int n_in,
                              void* d_out, int out_size) {
    const float* p1 = (const float*)d_in[0];
    const float* p2 = (const float*)d_in[1];
    const float* z1 = (const float*)d_in[2];
    const float* z2 = (const float*)d_in[3];
    const float* c1 = (const float*)d_in[4];
    const float* c2 = (const float*)d_in[5];
    float* out = (float*)d_out;

    cudaFuncSetAttribute(gemm_loss_kernel,
                         cudaFuncAttributeMaxDynamicSharedMemorySize, DYN_SMEM);

    zero_kernel<<<1, 64>>>();
    centers_kernel<<<NB, 1024>>>(c1, c2);
    prep_kernel<<<dim3(32, NB, 4), 256>>>(p1, p2, z1, z2);
    gemm_loss_kernel<<<dim3(8, 8, 64), 256, DYN_SMEM>>>();
    final_kernel<<<1, 1>>>(out);
}

// round 16
// speedup vs baseline: 1.1206x; 1.1206x over previous
#include <cuda_runtime.h>
#include <math.h>
#include <stdint.h>

// Problem constants (fixed by reference: N=32, C=256, H=W=32)
#define NB 32
#define CDIM 256
#define HW 1024
#define WD 32

// ---------------- device scratch (no allocations allowed) ----------------
__device__ double g_sum[64];                 // masked cos sum per (loss, n)
__device__ double g_cnt[64];                 // mask count per (loss, n)
__device__ float  g_ninv[4][NB * HW];        // 1/||.|| for p1,p2,z1,z2
__device__ float  g_cx[2][NB * HW];          // centers x for coord_1, coord_2
__device__ float  g_cy[2][NB * HW];          // centers y
__device__ float  g_dthr2[NB];               // EXACT d2 threshold (see below)
// TF32-quantized, transposed copies: [t][n][p][k], row = 256 floats (1KB).
__device__ float  g_tf32[4ull * NB * HW * CDIM];   // 134 MB

// Round fp32 -> TF32 (10-bit mantissa), same conversion cuBLAS/CUTLASS use.
__device__ __forceinline__ float tf32r(float x) {
    uint32_t u;
    asm("cvt.rna.tf32.f32 %0, %1;" : "=r"(u) : "f"(x));
    return __uint_as_float(u);
}

// m16n8k8 TF32 MMA, fp32 accumulate
__device__ __forceinline__ void mma_tf32(float* d,
                                         float a0, float a1, float a2, float a3,
                                         float b0, float b1) {
    asm volatile(
        "mma.sync.aligned.m16n8k8.row.col.f32.tf32.tf32.f32 "
        "{%0,%1,%2,%3}, {%4,%5,%6,%7}, {%8,%9}, {%0,%1,%2,%3};\n"
        : "+f"(d[0]), "+f"(d[1]), "+f"(d[2]), "+f"(d[3])
        : "r"(__float_as_uint(a0)), "r"(__float_as_uint(a1)),
          "r"(__float_as_uint(a2)), "r"(__float_as_uint(a3)),
          "r"(__float_as_uint(b0)), "r"(__float_as_uint(b1)));
}

#define CP_ASYNC16(dst32, srcp) \
    asm volatile("cp.async.cg.shared.global [%0], [%1], 16;\n" :: "r"(dst32), "l"(srcp))
#define CP_COMMIT() asm volatile("cp.async.commit_group;\n")
#define CP_WAIT(n)  asm volatile("cp.async.wait_group %0;\n" :: "n"(n))

// ---------------- kernels ----------------
__global__ void zero_kernel() {
    int i = threadIdx.x;
    if (i < 64) { g_sum[i] = 0.0; g_cnt[i] = 0.0; }
}

// grid (NB), block 1024: centers + EXACT d2 mask threshold.
// Reference mask  __fdiv_rn(__fsqrt_rn(d2), md) < 16  is monotone in d2, so
// a bit-level binary search yields T with mask <=> d2 < T, bit-exactly.
__global__ void centers_kernel(const float* __restrict__ c1, const float* __restrict__ c2) {
    int n = blockIdx.x;
    int p = threadIdx.x;
    float a0 = c1[n * 4 + 0], a1 = c1[n * 4 + 1], a2 = c1[n * 4 + 2], a3 = c1[n * 4 + 3];
    float b0 = c2[n * 4 + 0], b1 = c2[n * 4 + 1], b2 = c2[n * 4 + 2], b3 = c2[n * 4 + 3];
    float bw1 = __fdiv_rn(__fsub_rn(a2, a0), 32.0f), bh1 = __fdiv_rn(__fsub_rn(a3, a1), 32.0f);
    float bw2 = __fdiv_rn(__fsub_rn(b2, b0), 32.0f), bh2 = __fdiv_rn(__fsub_rn(b3, b1), 32.0f);
    float x = (float)(p % WD);
    float y = (float)(p / WD);
    g_cx[0][n * HW + p] = __fadd_rn(__fmul_rn(__fadd_rn(x, 0.5f), bw1), a0);
    g_cy[0][n * HW + p] = __fadd_rn(__fmul_rn(__fadd_rn(y, 0.5f), bh1), a1);
    g_cx[1][n * HW + p] = __fadd_rn(__fmul_rn(__fadd_rn(x, 0.5f), bw2), b0);
    g_cy[1][n * HW + p] = __fadd_rn(__fmul_rn(__fadd_rn(y, 0.5f), bh2), b1);
    if (p == 0) {
        float d1 = __fsqrt_rn(__fadd_rn(__fmul_rn(bw1, bw1), __fmul_rn(bh1, bh1)));
        float d2 = __fsqrt_rn(__fadd_rn(__fmul_rn(bw2, bw2), __fmul_rn(bh2, bh2)));
        float md = fmaxf(d1, d2);
        uint32_t lo = 0u, hi = 0x7F7FFFFFu;   // [0, FLT_MAX]
        while (lo < hi) {
            uint32_t mid = lo + ((hi - lo) >> 1);
            float v = __uint_as_float(mid);
            if (__fdiv_rn(__fsqrt_rn(v), md) >= 16.0f) hi = mid;
            else lo = mid + 1;
        }
        g_dthr2[n] = __uint_as_float(lo);     // mask <=> d2 < g_dthr2[n]
    }
}

// Fused prep: transpose [c][p] -> [p][c], TF32-quantize into g_tf32, AND
// accumulate exact-fp32 column norms (stored as inverses) in the same pass.
// grid (32 ptiles, NB, 4), block 256. 32x32 smem tile.
__global__ __launch_bounds__(256) void prep_kernel(
    const float* __restrict__ p1, const float* __restrict__ p2,
    const float* __restrict__ z1, const float* __restrict__ z2) {
    int t = blockIdx.z;
    int n = blockIdx.y;
    int p0 = blockIdx.x * 32;
    const float* src = (t == 0) ? p1 : (t == 1) ? p2 : (t == 2) ? z1 : z2;
    src += (size_t)n * CDIM * HW;
    float* dst = g_tf32 + ((size_t)(t * NB + n) * HW) * CDIM;

    __shared__ float s[32][33];
    __shared__ float part[8][32];
    int tid = threadIdx.x;
    int rc = tid >> 5;        // 0..7
    int rp = tid & 31;        // 0..31
    float acc = 0.f;

#pragma unroll 1
    for (int ct = 0; ct < 8; ++ct) {
        int c0 = ct * 32;
#pragma unroll
        for (int j = 0; j < 4; ++j) {
            int c = rc + j * 8;
            s[c][rp] = src[(size_t)(c0 + c) * HW + p0 + rp];
        }
        __syncthreads();
#pragma unroll
        for (int i = 0; i < 4; ++i) {
            float v = s[rc * 4 + i][rp];
            acc += v * v;
        }
#pragma unroll
        for (int j = 0; j < 4; ++j) {
            int p = rc + j * 8;
            dst[(size_t)(p0 + p) * CDIM + c0 + rp] = tf32r(s[rp][p]);
        }
        __syncthreads();
    }
    part[rc][rp] = acc;
    __syncthreads();
    if (tid < 32) {
        float n2 = 0.f;
#pragma unroll
        for (int g = 0; g < 8; ++g) n2 += part[g][tid];
        g_ninv[t][n * HW + p0 + tid] = 1.0f / sqrtf(n2);
    }
}

// Fused TF32 tensor-core GEMM + cosine + mask + masked-mean reduction.
// 128(p) x 128(q) tile. Ring of 3 slots, each slot = 32 k stored as TWO
// independent 16-k halves in the conflict-free [128][16] layout (row stride
// 16 floats interleaves fragment rows across bank halves). One barrier per
// 32-k slot (8 total). 8 warps (4M x 2N), warp tile 32x64. 2 CTAs/SM.
// MMA k-order identical to the BK=16 version (half 0 then half 1, ascending).
#define BM 128
#define BNQ 128
#define HK 16                 // half-slot k width
#define NSLOT 3
#define NS (CDIM / 32)        // 8 slots of 32 k
#define HALF_A (BM * HK)      // 2048 floats (8 KB)
#define SLOT_A (2 * HALF_A)   // 16 KB
#define HALF_B (BNQ * HK)
#define SLOT_B (2 * HALF_B)
#define DYN_SMEM (NSLOT * (SLOT_A + SLOT_B) * 4)   // 96 KB

__global__ __launch_bounds__(256, 2) void gemm_loss_kernel() {
    int z = blockIdx.z;          // 0..63 : (loss, n)
    int n = z & 31;
    int which = z >> 5;          // 0 -> (p1, z2), 1 -> (p2, z1)

    const float *Q, *K, *qiv, *kiv, *qcx, *qcy, *kcx, *kcy;
    if (which == 0) {
        Q = g_tf32 + ((size_t)(0 * NB + n) * HW) * CDIM;
        K = g_tf32 + ((size_t)(3 * NB + n) * HW) * CDIM;
        qiv = &g_ninv[0][n * HW]; kiv = &g_ninv[3][n * HW];
        qcx = &g_cx[0][n * HW]; qcy = &g_cy[0][n * HW];
        kcx = &g_cx[1][n * HW]; kcy = &g_cy[1][n * HW];
    } else {
        Q = g_tf32 + ((size_t)(1 * NB + n) * HW) * CDIM;
        K = g_tf32 + ((size_t)(2 * NB + n) * HW) * CDIM;
        qiv = &g_ninv[1][n * HW]; kiv = &g_ninv[2][n * HW];
        qcx = &g_cx[1][n * HW]; qcy = &g_cy[1][n * HW];
        kcx = &g_cx[0][n * HW]; kcy = &g_cy[0][n * HW];
    }
    float dthr2 = g_dthr2[n];

    extern __shared__ float dynsm[];
    float* Abase = dynsm;                         // NSLOT slots of [2][128][16]
    float* Bbase = dynsm + NSLOT * SLOT_A;        // NSLOT slots of [2][128][16]
    __shared__ float warpS[8];
    __shared__ int   warpC[8];

    int tid  = threadIdx.x;
    int lane = tid & 31;
    int warp = tid >> 5;          // 0..7
    int gid  = lane >> 2;         // 0..7
    int tig  = lane & 3;          // 0..3
    int warpM = warp >> 1;        // 0..3 -> 32-row band
    int warpN = warp & 1;         // 0..1 -> 64-col band
    int pBase = blockIdx.x * BM;
    int qBase = blockIdx.y * BNQ;

    // cp.async mapping within a 16-k half: cr = row (0..63), co = chunk col
    int cr = tid >> 2;            // 0..63
    int co = (tid & 3) * 4;       // 0,4,8,12

    uint32_t sA = (uint32_t)__cvta_generic_to_shared(Abase);
    uint32_t sB = (uint32_t)__cvta_generic_to_shared(Bbase);
    const uint32_t aSlotB = SLOT_A * 4;
    const uint32_t bSlotB = SLOT_B * 4;
    const uint32_t halfAB = HALF_A * 4;   // 8 KB
    const uint32_t halfBB = HALF_B * 4;
    uint32_t thOff = (uint32_t)((cr * HK + co) * 4);
    const float* qR = Q + (size_t)(pBase + cr) * CDIM + co;
    const float* kR = K + (size_t)(qBase + cr) * CDIM + co;

    float d[2][8][4];
#pragma unroll
    for (int mt = 0; mt < 2; ++mt)
#pragma unroll
        for (int nt = 0; nt < 8; ++nt)
#pragma unroll
            for (int r = 0; r < 4; ++r) d[mt][nt][r] = 0.f;

    // prologue: issue slots 0 and 1 as separate groups (8 cp.async each)
#pragma unroll
    for (int st = 0; st < 2; ++st) {
#pragma unroll
        for (int h = 0; h < 2; ++h) {
            int kc = st * 32 + h * HK;
            CP_ASYNC16(sA + st * aSlotB + h * halfAB + thOff,
                       qR + kc);
            CP_ASYNC16(sA + st * aSlotB + h * halfAB + thOff + 64u * HK * 4u,
                       qR + (size_t)64 * CDIM + kc);
            CP_ASYNC16(sB + st * bSlotB + h * halfBB + thOff,
                       kR + kc);
            CP_ASYNC16(sB + st * bSlotB + h * halfBB + thOff + 64u * HK * 4u,
                       kR + (size_t)64 * CDIM + kc);
        }
        CP_COMMIT();
    }

#pragma unroll
    for (int kt = 0; kt < NS; ++kt) {
        const int cur  = kt % NSLOT;
        const int nxt2 = (kt + 2) % NSLOT;
        if (kt < NS - 1) { CP_WAIT(1); } else { CP_WAIT(0); }
        __syncthreads();   // slot kt visible; fences reuse of slot nxt2
        if (kt + 2 < NS) {
#pragma unroll
            for (int h = 0; h < 2; ++h) {
                int kc = (kt + 2) * 32 + h * HK;
                CP_ASYNC16(sA + nxt2 * aSlotB + h * halfAB + thOff,
                           qR + kc);
                CP_ASYNC16(sA + nxt2 * aSlotB + h * halfAB + thOff + 64u * HK * 4u,
                           qR + (size_t)64 * CDIM + kc);
                CP_ASYNC16(sB + nxt2 * bSlotB + h * halfBB + thOff,
                           kR + kc);
                CP_ASYNC16(sB + nxt2 * bSlotB + h * halfBB + thOff + 64u * HK * 4u,
                           kR + (size_t)64 * CDIM + kc);
            }
            CP_COMMIT();
        }
        // compute the two 16-k halves in ascending k order (== BK=16 schedule)
#pragma unroll
        for (int h = 0; h < 2; ++h) {
            const float* Acur = Abase + cur * SLOT_A + h * HALF_A;
            const float* Bcur = Bbase + cur * SLOT_B + h * HALF_B;
            float4 wb[8];
#pragma unroll
            for (int nt = 0; nt < 8; ++nt)
                wb[nt] = *(const float4*)(Bcur + (warpN * 64 + nt * 8 + gid) * HK + tig * 4);
#pragma unroll
            for (int mt = 0; mt < 2; ++mt) {
                int pm = warpM * 32 + mt * 16 + gid;
                float4 va = *(const float4*)(Acur + pm * HK + tig * 4);
                float4 vb = *(const float4*)(Acur + (pm + 8) * HK + tig * 4);
#pragma unroll
                for (int nt = 0; nt < 8; ++nt)
                    mma_tf32(d[mt][nt], va.x, vb.x, va.y, vb.y, wb[nt].x, wb[nt].y);
#pragma unroll
                for (int nt = 0; nt < 8; ++nt)
                    mma_tf32(d[mt][nt], va.z, vb.z, va.w, vb.w, wb[nt].z, wb[nt].w);
            }
        }
    }

    // Epilogue. Premultiply accumulators by qinv (left-assoc identical to
    // d*qinv*kn), then cos = dpre*kn; mask = (d2 < dthr2) (bit-exact).
    float qnv[2][2], qxv[2][2], qyv[2][2];
#pragma unroll
    for (int mt = 0; mt < 2; ++mt)
#pragma unroll
        for (int i2 = 0; i2 < 2; ++i2) {
            int p = pBase + warpM * 32 + mt * 16 + gid + i2 * 8;
            qnv[mt][i2] = qiv[p]; qxv[mt][i2] = qcx[p]; qyv[mt][i2] = qcy[p];
        }
#pragma unroll
    for (int mt = 0; mt < 2; ++mt)
#pragma unroll
        for (int nt = 0; nt < 8; ++nt)
#pragma unroll
            for (int r = 0; r < 4; ++r)
                d[mt][nt][r] *= qnv[mt][r >> 1];

    float lsum = 0.f;
    int   icnt = 0;
#pragma unroll
    for (int nt = 0; nt < 8; ++nt) {
#pragma unroll
        for (int j2 = 0; j2 < 2; ++j2) {
            int q = qBase + warpN * 64 + nt * 8 + 2 * tig + j2;
            float kn = kiv[q], kx = kcx[q], ky = kcy[q];
#pragma unroll
            for (int mt = 0; mt < 2; ++mt) {
#pragma unroll
                for (int i2 = 0; i2 < 2; ++i2) {
                    float dx = __fsub_rn(qxv[mt][i2], kx);
                    float dy = __fsub_rn(qyv[mt][i2], ky);
                    float d2v = __fadd_rn(__fmul_rn(dx, dx), __fmul_rn(dy, dy));
                    if (d2v < dthr2) {
                        lsum += d[mt][nt][i2 * 2 + j2] * kn;
                        icnt += 1;
                    }
                }
            }
        }
    }

    // warp-shuffle reduction, then one cross-warp pass, then fp64 atomics
#pragma unroll
    for (int sh = 16; sh > 0; sh >>= 1) {
        lsum += __shfl_xor_sync(0xFFFFFFFFu, lsum, sh);
        icnt += __shfl_xor_sync(0xFFFFFFFFu, icnt, sh);
    }
    if (lane == 0) { warpS[warp] = lsum; warpC[warp] = icnt; }
    __syncthreads();
    if (warp == 0 && lane == 0) {
        float ts = 0.f; int tc = 0;
#pragma unroll
        for (int w = 0; w < 8; ++w) { ts += warpS[w]; tc += warpC[w]; }
        atomicAdd(&g_sum[z], (double)ts);
        atomicAdd(&g_cnt[z], (double)tc);
    }
}

__global__ void final_kernel(float* __restrict__ out) {
    double l1 = 0.0, l2 = 0.0;
    for (int n = 0; n < 32; ++n) {
        l1 += g_sum[n]      / (g_cnt[n]      + 1e-6);
        l2 += g_sum[32 + n] / (g_cnt[32 + n] + 1e-6);
    }
    out[0] = (float)(-((l1 / 32.0) + (l2 / 32.0)) * 0.5);
}

// ---------------- launch ----------------
extern "C" void kernel_launch(void* const* d_in, const int* in_sizes, int n_in,
                              void* d_out, int out_size) {
    const float* p1 = (const float*)d_in[0];
    const float* p2 = (const float*)d_in[1];
    const float* z1 = (const float*)d_in[2];
    const float* z2 = (const float*)d_in[3];
    const float* c1 = (const float*)d_in[4];
    const float* c2 = (const float*)d_in[5];
    float* out = (float*)d_out;

    cudaFuncSetAttribute(gemm_loss_kernel,
                         cudaFuncAttributeMaxDynamicSharedMemorySize, DYN_SMEM);

    zero_kernel<<<1, 64>>>();
    centers_kernel<<<NB, 1024>>>(c1, c2);
    prep_kernel<<<dim3(32, NB, 4), 256>>>(p1, p2, z1, z2);
    gemm_loss_kernel<<<dim3(8, 8, 64), 256, DYN_SMEM>>>();
    final_kernel<<<1, 1>>>(out);
}

// round 17
// speedup vs baseline: 1.1736x; 1.0474x over previous
#include <cuda_runtime.h>
#include <math.h>
#include <stdint.h>

// Problem constants (fixed by reference: N=32, C=256, H=W=32)
#define NB 32
#define CDIM 256
#define HW 1024
#define WD 32

// ---------------- device scratch (no allocations allowed) ----------------
__device__ double g_sum[64];                 // masked cos sum per (loss, n)
__device__ double g_cnt[64];                 // mask count per (loss, n)
__device__ float  g_ninv[4][NB * HW];        // 1/||.|| for p1,p2,z1,z2
__device__ float  g_cx[2][NB * HW];          // centers x for coord_1, coord_2
__device__ float  g_cy[2][NB * HW];          // centers y
__device__ float  g_dthr2[NB];               // EXACT d2 threshold (see below)
// TF32-quantized, transposed copies: [t][n][p][k], row = 256 floats (1KB).
__device__ float  g_tf32[4ull * NB * HW * CDIM];   // 134 MB

// Round fp32 -> TF32 (10-bit mantissa), same conversion cuBLAS/CUTLASS use.
__device__ __forceinline__ float tf32r(float x) {
    uint32_t u;
    asm("cvt.rna.tf32.f32 %0, %1;" : "=r"(u) : "f"(x));
    return __uint_as_float(u);
}

// m16n8k8 TF32 MMA, fp32 accumulate
__device__ __forceinline__ void mma_tf32(float* d,
                                         float a0, float a1, float a2, float a3,
                                         float b0, float b1) {
    asm volatile(
        "mma.sync.aligned.m16n8k8.row.col.f32.tf32.tf32.f32 "
        "{%0,%1,%2,%3}, {%4,%5,%6,%7}, {%8,%9}, {%0,%1,%2,%3};\n"
        : "+f"(d[0]), "+f"(d[1]), "+f"(d[2]), "+f"(d[3])
        : "r"(__float_as_uint(a0)), "r"(__float_as_uint(a1)),
          "r"(__float_as_uint(a2)), "r"(__float_as_uint(a3)),
          "r"(__float_as_uint(b0)), "r"(__float_as_uint(b1)));
}

#define CP_ASYNC16(dst32, srcp) \
    asm volatile("cp.async.cg.shared.global [%0], [%1], 16;\n" :: "r"(dst32), "l"(srcp))
#define CP_COMMIT() asm volatile("cp.async.commit_group;\n")
#define CP_WAIT(n)  asm volatile("cp.async.wait_group %0;\n" :: "n"(n))

// ---------------- kernels ----------------
__global__ void zero_kernel() {
    int i = threadIdx.x;
    if (i < 64) { g_sum[i] = 0.0; g_cnt[i] = 0.0; }
}

// grid (NB), block 1024: centers + EXACT d2 mask threshold.
// Reference mask  __fdiv_rn(__fsqrt_rn(d2), md) < 16  is monotone in d2, so
// a bit-level binary search yields T with mask <=> d2 < T, bit-exactly.
__global__ void centers_kernel(const float* __restrict__ c1, const float* __restrict__ c2) {
    int n = blockIdx.x;
    int p = threadIdx.x;
    float a0 = c1[n * 4 + 0], a1 = c1[n * 4 + 1], a2 = c1[n * 4 + 2], a3 = c1[n * 4 + 3];
    float b0 = c2[n * 4 + 0], b1 = c2[n * 4 + 1], b2 = c2[n * 4 + 2], b3 = c2[n * 4 + 3];
    float bw1 = __fdiv_rn(__fsub_rn(a2, a0), 32.0f), bh1 = __fdiv_rn(__fsub_rn(a3, a1), 32.0f);
    float bw2 = __fdiv_rn(__fsub_rn(b2, b0), 32.0f), bh2 = __fdiv_rn(__fsub_rn(b3, b1), 32.0f);
    float x = (float)(p % WD);
    float y = (float)(p / WD);
    g_cx[0][n * HW + p] = __fadd_rn(__fmul_rn(__fadd_rn(x, 0.5f), bw1), a0);
    g_cy[0][n * HW + p] = __fadd_rn(__fmul_rn(__fadd_rn(y, 0.5f), bh1), a1);
    g_cx[1][n * HW + p] = __fadd_rn(__fmul_rn(__fadd_rn(x, 0.5f), bw2), b0);
    g_cy[1][n * HW + p] = __fadd_rn(__fmul_rn(__fadd_rn(y, 0.5f), bh2), b1);
    if (p == 0) {
        float d1 = __fsqrt_rn(__fadd_rn(__fmul_rn(bw1, bw1), __fmul_rn(bh1, bh1)));
        float d2 = __fsqrt_rn(__fadd_rn(__fmul_rn(bw2, bw2), __fmul_rn(bh2, bh2)));
        float md = fmaxf(d1, d2);
        uint32_t lo = 0u, hi = 0x7F7FFFFFu;   // [0, FLT_MAX]
        while (lo < hi) {
            uint32_t mid = lo + ((hi - lo) >> 1);
            float v = __uint_as_float(mid);
            if (__fdiv_rn(__fsqrt_rn(v), md) >= 16.0f) hi = mid;
            else lo = mid + 1;
        }
        g_dthr2[n] = __uint_as_float(lo);     // mask <=> d2 < g_dthr2[n]
    }
}

// Fused prep: transpose [c][p] -> [p][c], TF32-quantize into g_tf32, AND
// accumulate exact-fp32 column norms (stored as inverses) in the same pass.
// grid (32 ptiles, NB, 4), block 256. 32x32 smem tile.
__global__ __launch_bounds__(256) void prep_kernel(
    const float* __restrict__ p1, const float* __restrict__ p2,
    const float* __restrict__ z1, const float* __restrict__ z2) {
    int t = blockIdx.z;
    int n = blockIdx.y;
    int p0 = blockIdx.x * 32;
    const float* src = (t == 0) ? p1 : (t == 1) ? p2 : (t == 2) ? z1 : z2;
    src += (size_t)n * CDIM * HW;
    float* dst = g_tf32 + ((size_t)(t * NB + n) * HW) * CDIM;

    __shared__ float s[32][33];
    __shared__ float part[8][32];
    int tid = threadIdx.x;
    int rc = tid >> 5;        // 0..7
    int rp = tid & 31;        // 0..31
    float acc = 0.f;

#pragma unroll 1
    for (int ct = 0; ct < 8; ++ct) {
        int c0 = ct * 32;
#pragma unroll
        for (int j = 0; j < 4; ++j) {
            int c = rc + j * 8;
            s[c][rp] = src[(size_t)(c0 + c) * HW + p0 + rp];
        }
        __syncthreads();
#pragma unroll
        for (int i = 0; i < 4; ++i) {
            float v = s[rc * 4 + i][rp];
            acc += v * v;
        }
#pragma unroll
        for (int j = 0; j < 4; ++j) {
            int p = rc + j * 8;
            dst[(size_t)(p0 + p) * CDIM + c0 + rp] = tf32r(s[rp][p]);
        }
        __syncthreads();
    }
    part[rc][rp] = acc;
    __syncthreads();
    if (tid < 32) {
        float n2 = 0.f;
#pragma unroll
        for (int g = 0; g < 8; ++g) n2 += part[g][tid];
        g_ninv[t][n * HW + p0 + tid] = 1.0f / sqrtf(n2);
    }
}

// Fused TF32 tensor-core GEMM + cosine + mask + masked-mean reduction.
// 128(p) x 128(q) tile, BK=16, 3-stage cp.async ring (one barrier/stage),
// 8 warps (4M x 2N), warp tile 32x64 (mt=2, nt=8). 2 CTAs/SM.
// Epilogue: dy^2 precomputed per (p-center, q-row) pair — 8 values reused
// across 64 outputs, bit-identical to recomputing per pair.
#define BM 128
#define BNQ 128
#define BK 16
#define NSTG 3
#define NT (CDIM / BK)    // 16 k-tiles
#define STAGE_A (BM * BK)              // floats
#define STAGE_B (BNQ * BK)             // floats
#define DYN_SMEM (NSTG * (STAGE_A + STAGE_B) * 4)   // 48 KB

__global__ __launch_bounds__(256, 2) void gemm_loss_kernel() {
    int z = blockIdx.z;          // 0..63 : (loss, n)
    int n = z & 31;
    int which = z >> 5;          // 0 -> (p1, z2), 1 -> (p2, z1)

    const float *Q, *K, *qiv, *kiv, *qcx, *qcy, *kcx, *kcy;
    if (which == 0) {
        Q = g_tf32 + ((size_t)(0 * NB + n) * HW) * CDIM;
        K = g_tf32 + ((size_t)(3 * NB + n) * HW) * CDIM;
        qiv = &g_ninv[0][n * HW]; kiv = &g_ninv[3][n * HW];
        qcx = &g_cx[0][n * HW]; qcy = &g_cy[0][n * HW];
        kcx = &g_cx[1][n * HW]; kcy = &g_cy[1][n * HW];
    } else {
        Q = g_tf32 + ((size_t)(1 * NB + n) * HW) * CDIM;
        K = g_tf32 + ((size_t)(2 * NB + n) * HW) * CDIM;
        qiv = &g_ninv[1][n * HW]; kiv = &g_ninv[2][n * HW];
        qcx = &g_cx[1][n * HW]; qcy = &g_cy[1][n * HW];
        kcx = &g_cx[0][n * HW]; kcy = &g_cy[0][n * HW];
    }
    float dthr2 = g_dthr2[n];

    extern __shared__ float dynsm[];
    float* Abase = dynsm;                         // NSTG stages of BM x BK
    float* Bbase = dynsm + NSTG * STAGE_A;        // NSTG stages of BNQ x BK
    __shared__ float warpS[8];
    __shared__ int   warpC[8];

    int tid  = threadIdx.x;
    int lane = tid & 31;
    int warp = tid >> 5;          // 0..7
    int gid  = lane >> 2;         // 0..7
    int tig  = lane & 3;          // 0..3
    int warpM = warp >> 1;        // 0..3 -> 32-row band
    int warpN = warp & 1;         // 0..1 -> 64-col band
    int pBase = blockIdx.x * BM;
    int qBase = blockIdx.y * BNQ;

    // cp.async mapping: cr = row (0..63), co = float offset of 16B chunk
    int cr = tid >> 2;            // 0..63
    int co = (tid & 3) * 4;       // 0,4,8,12

    uint32_t sA = (uint32_t)__cvta_generic_to_shared(Abase);
    uint32_t sB = (uint32_t)__cvta_generic_to_shared(Bbase);
    const uint32_t aBuf = STAGE_A * 4;    // 8 KB
    const uint32_t bBuf = STAGE_B * 4;    // 8 KB
    uint32_t thOff = (uint32_t)((cr * BK + co) * 4);
    const float* qRow0 = Q + (size_t)(pBase + cr) * CDIM + co;
    const float* qRow1 = Q + (size_t)(pBase + cr + 64) * CDIM + co;
    const float* kRow0 = K + (size_t)(qBase + cr) * CDIM + co;
    const float* kRow1 = K + (size_t)(qBase + cr + 64) * CDIM + co;

    float d[2][8][4];
#pragma unroll
    for (int mt = 0; mt < 2; ++mt)
#pragma unroll
        for (int nt = 0; nt < 8; ++nt)
#pragma unroll
            for (int r = 0; r < 4; ++r) d[mt][nt][r] = 0.f;

    // prologue: issue stages 0 and 1 as separate groups
#pragma unroll
    for (int st = 0; st < 2; ++st) {
        CP_ASYNC16(sA + st * aBuf + thOff,                 qRow0 + st * BK);
        CP_ASYNC16(sA + st * aBuf + thOff + 64u * BK * 4u, qRow1 + st * BK);
        CP_ASYNC16(sB + st * bBuf + thOff,                 kRow0 + st * BK);
        CP_ASYNC16(sB + st * bBuf + thOff + 64u * BK * 4u, kRow1 + st * BK);
        CP_COMMIT();
    }

#pragma unroll
    for (int kt = 0; kt < NT; ++kt) {
        const int cur  = kt % NSTG;
        const int nxt2 = (kt + 2) % NSTG;
        if (kt < NT - 1) { CP_WAIT(1); } else { CP_WAIT(0); }
        __syncthreads();   // stage kt visible; fences reuse of buffer nxt2
        if (kt + 2 < NT) {
            CP_ASYNC16(sA + nxt2 * aBuf + thOff,                 qRow0 + (kt + 2) * BK);
            CP_ASYNC16(sA + nxt2 * aBuf + thOff + 64u * BK * 4u, qRow1 + (kt + 2) * BK);
            CP_ASYNC16(sB + nxt2 * bBuf + thOff,                 kRow0 + (kt + 2) * BK);
            CP_ASYNC16(sB + nxt2 * bBuf + thOff + 64u * BK * 4u, kRow1 + (kt + 2) * BK);
            CP_COMMIT();
        }
        // B fragments: one float4 per nt covers both k8 steps (8 loads/warp)
        const float* Bcur = Bbase + cur * STAGE_B;
        const float* Acur = Abase + cur * STAGE_A;
        float4 wb[8];
#pragma unroll
        for (int nt = 0; nt < 8; ++nt)
            wb[nt] = *(const float4*)(Bcur + (warpN * 64 + nt * 8 + gid) * BK + tig * 4);
#pragma unroll
        for (int mt = 0; mt < 2; ++mt) {
            int pm = warpM * 32 + mt * 16 + gid;
            float4 va = *(const float4*)(Acur + pm * BK + tig * 4);
            float4 vb = *(const float4*)(Acur + (pm + 8) * BK + tig * 4);
#pragma unroll
            for (int nt = 0; nt < 8; ++nt)
                mma_tf32(d[mt][nt], va.x, vb.x, va.y, vb.y, wb[nt].x, wb[nt].y);
#pragma unroll
            for (int nt = 0; nt < 8; ++nt)
                mma_tf32(d[mt][nt], va.z, vb.z, va.w, vb.w, wb[nt].z, wb[nt].w);
        }
    }

    // Epilogue. Premultiply accumulators by qinv (left-assoc identical to
    // d*qinv*kn). Mask = (d2 < dthr2) with d2 = fadd(fmul(dx,dx), dy2) where
    // dy2 is precomputed per (p-center, q-row): the thread's 16 q's span
    // exactly 2 image rows and cy is constant along a row, so the 8 dy2
    // values are bit-identical to per-pair recomputation.
    float qnv[2][2], qxv[2][2], qyv[2][2];
#pragma unroll
    for (int mt = 0; mt < 2; ++mt)
#pragma unroll
        for (int i2 = 0; i2 < 2; ++i2) {
            int p = pBase + warpM * 32 + mt * 16 + gid + i2 * 8;
            qnv[mt][i2] = qiv[p]; qxv[mt][i2] = qcx[p]; qyv[mt][i2] = qcy[p];
        }
#pragma unroll
    for (int mt = 0; mt < 2; ++mt)
#pragma unroll
        for (int nt = 0; nt < 8; ++nt)
#pragma unroll
            for (int r = 0; r < 4; ++r)
                d[mt][nt][r] *= qnv[mt][r >> 1];

    // dy^2 per (4 p-centers) x (2 q-rows). q-row h covers nt in [4h, 4h+4).
    float dy2v[2][2][2];
#pragma unroll
    for (int h = 0; h < 2; ++h) {
        float kyrow = kcy[qBase + warpN * 64 + h * 32];   // constant along row
#pragma unroll
        for (int mt = 0; mt < 2; ++mt)
#pragma unroll
            for (int i2 = 0; i2 < 2; ++i2) {
                float dy = __fsub_rn(qyv[mt][i2], kyrow);
                dy2v[h][mt][i2] = __fmul_rn(dy, dy);
            }
    }

    float lsum = 0.f;
    int   icnt = 0;
#pragma unroll
    for (int nt = 0; nt < 8; ++nt) {
        const int h = nt >> 2;   // q-row index
#pragma unroll
        for (int j2 = 0; j2 < 2; ++j2) {
            int q = qBase + warpN * 64 + nt * 8 + 2 * tig + j2;
            float kn = kiv[q], kx = kcx[q];
#pragma unroll
            for (int mt = 0; mt < 2; ++mt) {
#pragma unroll
                for (int i2 = 0; i2 < 2; ++i2) {
                    float dx = __fsub_rn(qxv[mt][i2], kx);
                    float d2v = __fadd_rn(__fmul_rn(dx, dx), dy2v[h][mt][i2]);
                    if (d2v < dthr2) {
                        lsum += d[mt][nt][i2 * 2 + j2] * kn;
                        icnt += 1;
                    }
                }
            }
        }
    }

    // warp-shuffle reduction, then one cross-warp pass, then fp64 atomics
#pragma unroll
    for (int sh = 16; sh > 0; sh >>= 1) {
        lsum += __shfl_xor_sync(0xFFFFFFFFu, lsum, sh);
        icnt += __shfl_xor_sync(0xFFFFFFFFu, icnt, sh);
    }
    if (lane == 0) { warpS[warp] = lsum; warpC[warp] = icnt; }
    __syncthreads();
    if (warp == 0 && lane == 0) {
        float ts = 0.f; int tc = 0;
#pragma unroll
        for (int w = 0; w < 8; ++w) { ts += warpS[w]; tc += warpC[w]; }
        atomicAdd(&g_sum[z], (double)ts);
        atomicAdd(&g_cnt[z], (double)tc);
    }
}

__global__ void final_kernel(float* __restrict__ out) {
    double l1 = 0.0, l2 = 0.0;
    for (int n = 0; n < 32; ++n) {
        l1 += g_sum[n]      / (g_cnt[n]      + 1e-6);
        l2 += g_sum[32 + n] / (g_cnt[32 + n] + 1e-6);
    }
    out[0] = (float)(-((l1 / 32.0) + (l2 / 32.0)) * 0.5);
}

// ---------------- launch ----------------
extern "C" void kernel_launch(void* const* d_in, const int* in_sizes, int n_in,
                              void* d_out, int out_size) {
    const float* p1 = (const float*)d_in[0];
    const float* p2 = (const float*)d_in[1];
    const float* z1 = (const float*)d_in[2];
    const float* z2 = (const float*)d_in[3];
    const float* c1 = (const float*)d_in[4];
    const float* c2 = (const float*)d_in[5];
    float* out = (float*)d_out;

    cudaFuncSetAttribute(gemm_loss_kernel,
                         cudaFuncAttributeMaxDynamicSharedMemorySize, DYN_SMEM);

    zero_kernel<<<1, 64>>>();
    centers_kernel<<<NB, 1024>>>(c1, c2);
    prep_kernel<<<dim3(32, NB, 4), 256>>>(p1, p2, z1, z2);
    gemm_loss_kernel<<<dim3(8, 8, 64), 256, DYN_SMEM>>>();
    final_kernel<<<1, 1>>>(out);
}